// round 6
// baseline (speedup 1.0000x reference)
#include <cuda_runtime.h>
#include <cuda_bf16.h>
#include <cstdint>

#define BB 8
#define SS 2048
#define DD 1024
#define HH 64
#define MM (BB*SS)

// Scratch: Q hi only (pre-scaled by log2e/32); K,V split hi/lo
__device__ __align__(16) __nv_bfloat16 g_Qh[MM*HH];
__device__ __align__(16) __nv_bfloat16 g_Kh[MM*HH];
__device__ __align__(16) __nv_bfloat16 g_Kl[MM*HH];
__device__ __align__(16) __nv_bfloat16 g_Vh[MM*HH];
__device__ __align__(16) __nv_bfloat16 g_Vl[MM*HH];
// W split: [3][64][1024], mat order {Q,K,V}
__device__ __align__(16) __nv_bfloat16 g_Wh[3*HH*DD];
__device__ __align__(16) __nv_bfloat16 g_Wl[3*HH*DD];

// ---------------------------------------------------------------------------
// helpers
// ---------------------------------------------------------------------------
__device__ __forceinline__ uint32_t pack2(float lo, float hi) {
    uint32_t r;
    asm("cvt.rn.bf16x2.f32 %0, %1, %2;" : "=r"(r) : "f"(hi), "f"(lo));
    return r;
}
// round-to-nearest split (used where hi error is NOT compensated: Q, W)
__device__ __forceinline__ void split_pair(float x0, float x1, uint32_t& h, uint32_t& l) {
    float h0 = __bfloat162float(__float2bfloat16_rn(x0));
    float h1 = __bfloat162float(__float2bfloat16_rn(x1));
    h = pack2(h0, h1);
    l = pack2(x0 - h0, x1 - h1);
}
// truncation split (hi = upper 16 bits, lo exact residual) — cheaper; use only
// where the lo term participates so hi error is compensated (X, K, V, P).
__device__ __forceinline__ void split_trunc(float x0, float x1, uint32_t& h, uint32_t& l) {
    uint32_t b0 = __float_as_uint(x0), b1 = __float_as_uint(x1);
    h = __byte_perm(b0, b1, 0x7632);  // {b1.hi, b0.hi} -> low half = x0
    float h0 = __int_as_float(b0 & 0xFFFF0000u);
    float h1 = __int_as_float(b1 & 0xFFFF0000u);
    l = pack2(x0 - h0, x1 - h1);
}

__device__ __forceinline__ void ldm_x4(uint32_t* r, uint32_t addr) {
    asm volatile("ldmatrix.sync.aligned.m8n8.x4.shared.b16 {%0,%1,%2,%3}, [%4];"
                 : "=r"(r[0]), "=r"(r[1]), "=r"(r[2]), "=r"(r[3]) : "r"(addr));
}
__device__ __forceinline__ void ldm_x4_t(uint32_t* r, uint32_t addr) {
    asm volatile("ldmatrix.sync.aligned.m8n8.x4.trans.shared.b16 {%0,%1,%2,%3}, [%4];"
                 : "=r"(r[0]), "=r"(r[1]), "=r"(r[2]), "=r"(r[3]) : "r"(addr));
}

__device__ __forceinline__ void cp16(uint32_t dst, const void* src) {
    asm volatile("cp.async.cg.shared.global [%0], [%1], 16;"
                 :: "r"(dst), "l"(src) : "memory");
}
#define CP_COMMIT() asm volatile("cp.async.commit_group;" ::: "memory")
#define CP_WAIT0()  asm volatile("cp.async.wait_group 0;" ::: "memory")
#define CP_WAIT1()  asm volatile("cp.async.wait_group 1;" ::: "memory")

// smem bf16 tiles: row stride 144 bytes (72 bf16) -> ldmatrix conflict-free
#define LDB 144

__device__ __forceinline__ uint32_t ldm_addr(uint32_t base, int row0, int col0) {
    int l = threadIdx.x & 31;
    int r = row0 + (l & 7) + ((l >> 3) & 1) * 8;
    int c = col0 + (l >> 4) * 8;
    return base + r * LDB + c * 2;
}
__device__ __forceinline__ uint32_t ldm_addr_b(uint32_t base, int row0, int col0) {
    int l = threadIdx.x & 31;
    int r = row0 + (l & 7) + (l >> 4) * 8;
    int c = col0 + ((l >> 3) & 1) * 8;
    return base + r * LDB + c * 2;
}

__device__ __forceinline__ void mma_bf16(float* d, const uint32_t* a, const uint32_t* b) {
    asm volatile(
        "mma.sync.aligned.m16n8k16.row.col.f32.bf16.bf16.f32 "
        "{%0,%1,%2,%3}, {%4,%5,%6,%7}, {%8,%9}, {%0,%1,%2,%3};"
        : "+f"(d[0]), "+f"(d[1]), "+f"(d[2]), "+f"(d[3])
        : "r"(a[0]), "r"(a[1]), "r"(a[2]), "r"(a[3]), "r"(b[0]), "r"(b[1]));
}

// 2^x via magic-round + deg-4 Taylor; valid for x <= ~30, clamps below -126.
__device__ __forceinline__ float fast_exp2(float x) {
    x = fmaxf(x, -126.0f);
    float r = x + 12582912.0f;
    int ik = __float_as_int(r) - 0x4B400000;
    float f = x - (r - 12582912.0f);
    float p = fmaf(0.0096180f, f, 0.0555041f);
    p = fmaf(p, f, 0.2402265f);
    p = fmaf(p, f, 0.6931472f);
    p = fmaf(p, f, 1.0f);
    return __int_as_float(__float_as_int(p) + (ik << 23));
}

// ---------------------------------------------------------------------------
// prep_w: split weights into bf16 hi/lo (rn). grid (32,3), 8 f32/thread, MLP 2.
// ---------------------------------------------------------------------------
__global__ __launch_bounds__(256) void prep_w(const float* __restrict__ Wq,
                                              const float* __restrict__ Wk,
                                              const float* __restrict__ Wv) {
    int mat = blockIdx.y;
    const float* W = (mat == 0) ? Wq : ((mat == 1) ? Wk : Wv);
    int i = blockIdx.x * 2048 + threadIdx.x * 8;
    float4 v0 = *reinterpret_cast<const float4*>(W + i);
    float4 v1 = *reinterpret_cast<const float4*>(W + i + 4);
    uint32_t h0, l0, h1, l1, h2, l2, h3, l3;
    split_pair(v0.x, v0.y, h0, l0);
    split_pair(v0.z, v0.w, h1, l1);
    split_pair(v1.x, v1.y, h2, l2);
    split_pair(v1.z, v1.w, h3, l3);
    size_t o = ((size_t)mat * HH * DD + i) >> 1;
    uint32_t* ph = reinterpret_cast<uint32_t*>(g_Wh);
    uint32_t* pl = reinterpret_cast<uint32_t*>(g_Wl);
    ph[o + 0] = h0; ph[o + 1] = h1; ph[o + 2] = h2; ph[o + 3] = h3;
    pl[o + 0] = l0; pl[o + 1] = l1; pl[o + 2] = l2; pl[o + 3] = l3;
}

// ---------------------------------------------------------------------------
// proj: Q,K,V = X @ W^T via split-bf16 mma. CTA = 64 rows; 256 CTAs, 8 warps.
// Q: 2-term, hi-only output. K,V: 3-term, split output.
// X staged via 2-stage cp.async (raw f32), split on readback.
// ---------------------------------------------------------------------------
#define PTM 64
#define PXH 0
#define PXL 9216
#define PWH 18432
#define PWL 46080
#define PF32 73728                    // 2 stages x 16 KB raw X
#define PTOT (PF32 + 2 * 16384)      // 106496

__global__ __launch_bounds__(256) void proj_tc(const float* __restrict__ X) {
    extern __shared__ char sm[];
    const uint32_t sb = (uint32_t)__cvta_generic_to_shared(sm);
    const int tid = threadIdx.x, wid = tid >> 5, lane = tid & 31;
    const int g = lane >> 2, t = lane & 3;
    const int wm = wid >> 2, wn = wid & 3;
    const int m0 = blockIdx.x * PTM;

    // prologue: stage chunks 0 and 1
    #pragma unroll
    for (int st = 0; st < 2; st++) {
        #pragma unroll
        for (int i = 0; i < 4; i++) {
            int id = tid + i * 256;
            int row = id >> 4, seg = id & 15;
            cp16(sb + PF32 + st * 16384 + row * 256 + seg * 16,
                 X + (size_t)(m0 + row) * DD + st * 64 + seg * 4);
        }
        CP_COMMIT();
    }

    float acc[3][2][2][4];
    #pragma unroll
    for (int a = 0; a < 3; a++)
        #pragma unroll
        for (int b = 0; b < 2; b++)
            #pragma unroll
            for (int c = 0; c < 2; c++)
                #pragma unroll
                for (int d = 0; d < 4; d++) acc[a][b][c][d] = 0.f;

    for (int kc = 0; kc < 16; kc++) {
        const int kbase = kc * 64;
        CP_WAIT1();   // stage kc arrived (own-thread data only -> no sync needed)

        // read staged X, split (trunc: lo compensates), store bf16 planes
        #pragma unroll
        for (int i = 0; i < 4; i++) {
            int id = tid + i * 256;
            int row = id >> 4, seg = id & 15;
            float4 v = *reinterpret_cast<const float4*>(
                sm + PF32 + (kc & 1) * 16384 + row * 256 + seg * 16);
            uint32_t h0, l0, h1, l1;
            split_trunc(v.x, v.y, h0, l0);
            split_trunc(v.z, v.w, h1, l1);
            uint32_t off = row * LDB + seg * 8;
            *reinterpret_cast<uint32_t*>(sm + PXH + off)     = h0;
            *reinterpret_cast<uint32_t*>(sm + PXH + off + 4) = h1;
            *reinterpret_cast<uint32_t*>(sm + PXL + off)     = l0;
            *reinterpret_cast<uint32_t*>(sm + PXL + off + 4) = l1;
        }
        // W chunk: 192 rows x 64 bf16 (hi and lo), L2-hot LDG
        #pragma unroll
        for (int i = 0; i < 12; i++) {
            int id = tid + i * 256;
            int hl = (id >= 1536);
            int rem = id - hl * 1536;
            int row = rem >> 3, c = rem & 7;
            const __nv_bfloat16* src = hl ? g_Wl : g_Wh;
            uint4 v = *reinterpret_cast<const uint4*>(src + (size_t)row * DD + kbase + c * 8);
            *reinterpret_cast<uint4*>(sm + (hl ? PWL : PWH) + row * LDB + c * 16) = v;
        }
        __syncthreads();

        // stage chunk kc+2 (own staging slot: safe after own reads above)
        if (kc < 14) {
            const int kn = (kc + 2) * 64;
            #pragma unroll
            for (int i = 0; i < 4; i++) {
                int id = tid + i * 256;
                int row = id >> 4, seg = id & 15;
                cp16(sb + PF32 + (kc & 1) * 16384 + row * 256 + seg * 16,
                     X + (size_t)(m0 + row) * DD + kn + seg * 4);
            }
        }
        CP_COMMIT();   // commit every iter (possibly empty) to keep ring arithmetic

        #pragma unroll
        for (int ks = 0; ks < 4; ks++) {
            uint32_t ah[2][4], al[2][4];
            #pragma unroll
            for (int fm = 0; fm < 2; fm++) {
                ldm_x4(ah[fm], ldm_addr(sb + PXH, wm * 32 + fm * 16, ks * 16));
                ldm_x4(al[fm], ldm_addr(sb + PXL, wm * 32 + fm * 16, ks * 16));
            }
            #pragma unroll
            for (int mat = 0; mat < 3; mat++) {
                uint32_t bh[4], bl[4];
                ldm_x4(bh, ldm_addr_b(sb + PWH, mat * 64 + wn * 16, ks * 16));
                if (mat) ldm_x4(bl, ldm_addr_b(sb + PWL, mat * 64 + wn * 16, ks * 16));
                #pragma unroll
                for (int fm = 0; fm < 2; fm++)
                    #pragma unroll
                    for (int fn = 0; fn < 2; fn++) {
                        mma_bf16(acc[mat][fm][fn], ah[fm], &bh[fn * 2]);
                        if (mat) mma_bf16(acc[mat][fm][fn], ah[fm], &bl[fn * 2]);
                        mma_bf16(acc[mat][fm][fn], al[fm], &bh[fn * 2]);
                    }
            }
        }
        __syncthreads();
    }

    // epilogue: Q -> hi only (rn) with log2e/32 scale; K,V -> trunc split
    {
        const float scl = 1.44269504f / 32.0f;
        #pragma unroll
        for (int fm = 0; fm < 2; fm++)
            #pragma unroll
            for (int fn = 0; fn < 2; fn++) {
                const float* c = acc[0][fm][fn];
                int r0 = m0 + wm * 32 + fm * 16 + g;
                int col = wn * 16 + fn * 8 + t * 2;
                reinterpret_cast<uint32_t*>(g_Qh)[((size_t)r0 * HH + col) >> 1] =
                    pack2(c[0] * scl, c[1] * scl);
                reinterpret_cast<uint32_t*>(g_Qh)[((size_t)(r0 + 8) * HH + col) >> 1] =
                    pack2(c[2] * scl, c[3] * scl);
            }
    }
    #pragma unroll
    for (int mat = 1; mat < 3; mat++) {
        __nv_bfloat16* gh = (mat == 1) ? g_Kh : g_Vh;
        __nv_bfloat16* gl = (mat == 1) ? g_Kl : g_Vl;
        #pragma unroll
        for (int fm = 0; fm < 2; fm++)
            #pragma unroll
            for (int fn = 0; fn < 2; fn++) {
                const float* c = acc[mat][fm][fn];
                int r0 = m0 + wm * 32 + fm * 16 + g;
                int col = wn * 16 + fn * 8 + t * 2;
                uint32_t h, l;
                split_trunc(c[0], c[1], h, l);
                reinterpret_cast<uint32_t*>(gh)[((size_t)r0 * HH + col) >> 1] = h;
                reinterpret_cast<uint32_t*>(gl)[((size_t)r0 * HH + col) >> 1] = l;
                split_trunc(c[2], c[3], h, l);
                reinterpret_cast<uint32_t*>(gh)[((size_t)(r0 + 8) * HH + col) >> 1] = h;
                reinterpret_cast<uint32_t*>(gl)[((size_t)(r0 + 8) * HH + col) >> 1] = l;
            }
    }
}

// ---------------------------------------------------------------------------
// attn: flash attention, no-max softmax, register P, 2-stage cp.async pipeline.
// 1D grid of 256 CTAs, balanced (qt,b) schedule. 256 thr, warps 4 qw x 2 kw.
// ---------------------------------------------------------------------------
#define AQ    0
#define PLANE 9216
#define ABUF  9216
#define STG   (4 * PLANE)
#define ALR   (ABUF + 2 * STG)
#define ATOT  (ALR + 512)

__global__ __launch_bounds__(256, 2) void attn_tc(float* __restrict__ Outp) {
    extern __shared__ char sm[];
    const uint32_t sb = (uint32_t)__cvta_generic_to_shared(sm);
    const int tid = threadIdx.x, wid = tid >> 5, lane = tid & 31;
    const int g = lane >> 2, t = lane & 3;
    const int qw = wid >> 1, kw = wid & 1;

    const int bid = blockIdx.x;
    int qt, b;
    if (bid < 108)      { qt = bid % 27;            b = bid / 27; }
    else if (bid < 148) { int s = bid - 108;        qt = 27 + (s >> 3); b = s & 7; }
    else                { int p = bid - 148;        qt = 26 - (p % 27); b = (p / 27) + 4; }

    const int q0 = qt * 64;
    const size_t base = (size_t)b * SS;

    {
        #pragma unroll
        for (int i = 0; i < 8; i++) {
            int id = tid + i * 256;
            int plane = id >> 9, rem = id & 511;
            int row = rem >> 3, c = rem & 7;
            const __nv_bfloat16* src =
                (plane == 0) ? g_Kh : ((plane == 1) ? g_Kl : ((plane == 2) ? g_Vh : g_Vl));
            cp16(sb + ABUF + plane * PLANE + row * LDB + c * 16,
                 src + (base + row) * HH + c * 8);
        }
    }
    CP_COMMIT();

    #pragma unroll
    for (int i = 0; i < 2; i++) {
        int id = tid + i * 256;
        int row = id >> 3, c = id & 7;
        *reinterpret_cast<uint4*>(sm + AQ + row * LDB + c * 16) =
            *reinterpret_cast<const uint4*>(g_Qh + (base + q0 + row) * HH + c * 8);
    }

    float o[8][4];
    #pragma unroll
    for (int i = 0; i < 8; i++)
        #pragma unroll
        for (int j = 0; j < 4; j++) o[i][j] = 0.f;
    float lsum0 = 0.f, lsum1 = 0.f;

    for (int kt = 0; kt <= qt; kt++) {
        const int k0 = kt * 64;
        CP_WAIT0();
        __syncthreads();

        if (kt < qt) {
            const int kn = k0 + 64;
            const uint32_t dstg = sb + ABUF + ((kt + 1) & 1) * STG;
            #pragma unroll
            for (int i = 0; i < 8; i++) {
                int id = tid + i * 256;
                int plane = id >> 9, rem = id & 511;
                int row = rem >> 3, c = rem & 7;
                const __nv_bfloat16* src =
                    (plane == 0) ? g_Kh : ((plane == 1) ? g_Kl : ((plane == 2) ? g_Vh : g_Vl));
                cp16(dstg + plane * PLANE + row * LDB + c * 16,
                     src + (base + kn + row) * HH + c * 8);
            }
        }
        CP_COMMIT();

        const uint32_t stg = sb + ABUF + (kt & 1) * STG;
        const uint32_t sKH = stg, sKL = stg + PLANE, sVH = stg + 2 * PLANE, sVL = stg + 3 * PLANE;

        float s[4][4];
        #pragma unroll
        for (int i = 0; i < 4; i++)
            #pragma unroll
            for (int j = 0; j < 4; j++) s[i][j] = 0.f;

        #pragma unroll
        for (int hs = 0; hs < 4; hs++) {
            uint32_t ah[4], bh[4], bl[4], bh2[4], bl2[4];
            ldm_x4(ah, ldm_addr(sb + AQ, qw * 16, hs * 16));
            ldm_x4(bh,  ldm_addr_b(sKH, kw * 32,      hs * 16));
            ldm_x4(bl,  ldm_addr_b(sKL, kw * 32,      hs * 16));
            ldm_x4(bh2, ldm_addr_b(sKH, kw * 32 + 16, hs * 16));
            ldm_x4(bl2, ldm_addr_b(sKL, kw * 32 + 16, hs * 16));
            #pragma unroll
            for (int fn = 0; fn < 2; fn++) {
                mma_bf16(s[fn],     ah, &bh[fn * 2]);
                mma_bf16(s[fn],     ah, &bl[fn * 2]);
                mma_bf16(s[2 + fn], ah, &bh2[fn * 2]);
                mma_bf16(s[2 + fn], ah, &bl2[fn * 2]);
            }
        }

        if (kt == qt) {
            #pragma unroll
            for (int f = 0; f < 4; f++) {
                int kg = k0 + kw * 32 + f * 8 + t * 2;
                int qg0 = q0 + qw * 16 + g, qg1 = qg0 + 8;
                if (kg     > qg0) s[f][0] = -200.f;
                if (kg + 1 > qg0) s[f][1] = -200.f;
                if (kg     > qg1) s[f][2] = -200.f;
                if (kg + 1 > qg1) s[f][3] = -200.f;
            }
        }

        uint32_t pah[2][4], pal[2][4];
        #pragma unroll
        for (int ks2 = 0; ks2 < 2; ks2++) {
            #pragma unroll
            for (int ff = 0; ff < 2; ff++) {
                const int f = ks2 * 2 + ff;
                float p0 = fast_exp2(s[f][0]);
                float p1 = fast_exp2(s[f][1]);
                float p2 = fast_exp2(s[f][2]);
                float p3 = fast_exp2(s[f][3]);
                lsum0 += p0 + p1;
                lsum1 += p2 + p3;
                split_trunc(p0, p1, pah[ks2][ff * 2],     pal[ks2][ff * 2]);
                split_trunc(p2, p3, pah[ks2][ff * 2 + 1], pal[ks2][ff * 2 + 1]);
            }
        }

        #pragma unroll
        for (int ks2 = 0; ks2 < 2; ks2++) {
            uint32_t vh[4][4], vl[4][4];
            #pragma unroll
            for (int c = 0; c < 4; c++) {
                ldm_x4_t(vh[c], ldm_addr(sVH, kw * 32 + ks2 * 16, c * 16));
                ldm_x4_t(vl[c], ldm_addr(sVL, kw * 32 + ks2 * 16, c * 16));
            }
            #pragma unroll
            for (int j = 0; j < 8; j++) {
                const uint32_t* bvh = &vh[j >> 1][(j & 1) * 2];
                const uint32_t* bvl = &vl[j >> 1][(j & 1) * 2];
                mma_bf16(o[j], pah[ks2], bvh);
                mma_bf16(o[j], pal[ks2], bvh);
                mma_bf16(o[j], pah[ks2], bvl);
            }
        }
    }
    __syncthreads();

    lsum0 += __shfl_xor_sync(0xFFFFFFFFu, lsum0, 1);
    lsum0 += __shfl_xor_sync(0xFFFFFFFFu, lsum0, 2);
    lsum1 += __shfl_xor_sync(0xFFFFFFFFu, lsum1, 1);
    lsum1 += __shfl_xor_sync(0xFFFFFFFFu, lsum1, 2);
    float* lred = reinterpret_cast<float*>(sm + ALR);
    if (t == 0) {
        lred[(qw * 2 + kw) * 16 + g]     = lsum0;
        lred[(qw * 2 + kw) * 16 + 8 + g] = lsum1;
    }
    float* ored = reinterpret_cast<float*>(sm);
    if (kw == 1) {
        #pragma unroll
        for (int j = 0; j < 8; j++) {
            int col = j * 8 + t * 2;
            *reinterpret_cast<float2*>(&ored[(qw * 16 + g) * 64 + col]) =
                make_float2(o[j][0], o[j][1]);
            *reinterpret_cast<float2*>(&ored[(qw * 16 + g + 8) * 64 + col]) =
                make_float2(o[j][2], o[j][3]);
        }
    }
    __syncthreads();

    if (kw == 0) {
        float inv0 = 1.f / (lred[(qw * 2) * 16 + g]     + lred[(qw * 2 + 1) * 16 + g]);
        float inv1 = 1.f / (lred[(qw * 2) * 16 + 8 + g] + lred[(qw * 2 + 1) * 16 + 8 + g]);
        #pragma unroll
        for (int j = 0; j < 8; j++) {
            int col = j * 8 + t * 2;
            float2 a0 = *reinterpret_cast<float2*>(&ored[(qw * 16 + g) * 64 + col]);
            float2 a1 = *reinterpret_cast<float2*>(&ored[(qw * 16 + g + 8) * 64 + col]);
            size_t r0 = (base + q0 + qw * 16 + g) * HH + col;
            *reinterpret_cast<float2*>(Outp + r0) =
                make_float2((o[j][0] + a0.x) * inv0, (o[j][1] + a0.y) * inv0);
            *reinterpret_cast<float2*>(Outp + r0 + 8 * HH) =
                make_float2((o[j][2] + a1.x) * inv1, (o[j][3] + a1.y) * inv1);
        }
    }
}

// ---------------------------------------------------------------------------
extern "C" void kernel_launch(void* const* d_in, const int* in_sizes, int n_in,
                              void* d_out, int out_size)
{
    const float* X  = (const float*)d_in[0];
    const float* Wk = (const float*)d_in[1];
    const float* Wq = (const float*)d_in[2];
    const float* Wv = (const float*)d_in[3];
    float* Out = (float*)d_out;
    (void)in_sizes; (void)n_in; (void)out_size;

    cudaFuncSetAttribute(proj_tc, cudaFuncAttributeMaxDynamicSharedMemorySize, PTOT);
    cudaFuncSetAttribute(attn_tc, cudaFuncAttributeMaxDynamicSharedMemorySize, ATOT);

    prep_w<<<dim3(32, 3), 256>>>(Wq, Wk, Wv);
    proj_tc<<<MM / PTM, 256, PTOT>>>(X);
    attn_tc<<<256, 256, ATOT>>>(Out);
}

// round 7
// speedup vs baseline: 1.2408x; 1.2408x over previous
#include <cuda_runtime.h>
#include <cuda_fp16.h>
#include <cstdint>

#define BB 8
#define SS 2048
#define DD 1024
#define HH 64
#define MM (BB*SS)

// Scratch (fp16): Q hi only (pre-scaled by log2e/32); K,V split hi/lo
__device__ __align__(16) __half g_Qh[MM*HH];
__device__ __align__(16) __half g_Kh[MM*HH];
__device__ __align__(16) __half g_Kl[MM*HH];
__device__ __align__(16) __half g_Vh[MM*HH];
__device__ __align__(16) __half g_Vl[MM*HH];
// W split: [3][64][1024], mat order {Q,K,V}
__device__ __align__(16) __half g_Wh[3*HH*DD];
__device__ __align__(16) __half g_Wl[3*HH*DD];

// ---------------------------------------------------------------------------
// helpers
// ---------------------------------------------------------------------------
__device__ __forceinline__ uint32_t pack2h(float lo, float hi) {
    uint32_t r;
    asm("cvt.rn.f16x2.f32 %0, %1, %2;" : "=r"(r) : "f"(hi), "f"(lo));
    return r;
}
// fp16 round-to-nearest split: h = rn(x), l = rn(x - h) (second rounding ~2^-22)
__device__ __forceinline__ void split_pair_h(float x0, float x1, uint32_t& h, uint32_t& l) {
    float h0 = __half2float(__float2half_rn(x0));
    float h1 = __half2float(__float2half_rn(x1));
    h = pack2h(h0, h1);
    l = pack2h(x0 - h0, x1 - h1);
}

__device__ __forceinline__ void ldm_x4(uint32_t* r, uint32_t addr) {
    asm volatile("ldmatrix.sync.aligned.m8n8.x4.shared.b16 {%0,%1,%2,%3}, [%4];"
                 : "=r"(r[0]), "=r"(r[1]), "=r"(r[2]), "=r"(r[3]) : "r"(addr));
}
__device__ __forceinline__ void ldm_x4_t(uint32_t* r, uint32_t addr) {
    asm volatile("ldmatrix.sync.aligned.m8n8.x4.trans.shared.b16 {%0,%1,%2,%3}, [%4];"
                 : "=r"(r[0]), "=r"(r[1]), "=r"(r[2]), "=r"(r[3]) : "r"(addr));
}

__device__ __forceinline__ void cp16(uint32_t dst, const void* src) {
    asm volatile("cp.async.cg.shared.global [%0], [%1], 16;"
                 :: "r"(dst), "l"(src) : "memory");
}
#define CP_COMMIT() asm volatile("cp.async.commit_group;" ::: "memory")
#define CP_WAIT0()  asm volatile("cp.async.wait_group 0;" ::: "memory")

// smem fp16 tiles: row stride 144 bytes (72 halves) -> ldmatrix conflict-free
#define LDB 144

__device__ __forceinline__ uint32_t ldm_addr(uint32_t base, int row0, int col0) {
    int l = threadIdx.x & 31;
    int r = row0 + (l & 7) + ((l >> 3) & 1) * 8;
    int c = col0 + (l >> 4) * 8;
    return base + r * LDB + c * 2;
}
__device__ __forceinline__ uint32_t ldm_addr_b(uint32_t base, int row0, int col0) {
    int l = threadIdx.x & 31;
    int r = row0 + (l & 7) + (l >> 4) * 8;
    int c = col0 + ((l >> 3) & 1) * 8;
    return base + r * LDB + c * 2;
}

__device__ __forceinline__ void mma_f16(float* d, const uint32_t* a, const uint32_t* b) {
    asm volatile(
        "mma.sync.aligned.m16n8k16.row.col.f32.f16.f16.f32 "
        "{%0,%1,%2,%3}, {%4,%5,%6,%7}, {%8,%9}, {%0,%1,%2,%3};"
        : "+f"(d[0]), "+f"(d[1]), "+f"(d[2]), "+f"(d[3])
        : "r"(a[0]), "r"(a[1]), "r"(a[2]), "r"(a[3]), "r"(b[0]), "r"(b[1]));
}

// 2^x via magic-round + deg-4 Taylor; clamps below -126.
__device__ __forceinline__ float fast_exp2(float x) {
    x = fmaxf(x, -126.0f);
    float r = x + 12582912.0f;
    int ik = __float_as_int(r) - 0x4B400000;
    float f = x - (r - 12582912.0f);
    float p = fmaf(0.0096180f, f, 0.0555041f);
    p = fmaf(p, f, 0.2402265f);
    p = fmaf(p, f, 0.6931472f);
    p = fmaf(p, f, 1.0f);
    return __int_as_float(__float_as_int(p) + (ik << 23));
}

// ---------------------------------------------------------------------------
// prep_w: split weights into fp16 hi/lo (rn). grid (32,3), 8 f32/thread.
// ---------------------------------------------------------------------------
__global__ __launch_bounds__(256) void prep_w(const float* __restrict__ Wq,
                                              const float* __restrict__ Wk,
                                              const float* __restrict__ Wv) {
    int mat = blockIdx.y;
    const float* W = (mat == 0) ? Wq : ((mat == 1) ? Wk : Wv);
    int i = blockIdx.x * 2048 + threadIdx.x * 8;
    float4 v0 = *reinterpret_cast<const float4*>(W + i);
    float4 v1 = *reinterpret_cast<const float4*>(W + i + 4);
    uint32_t h0, l0, h1, l1, h2, l2, h3, l3;
    split_pair_h(v0.x, v0.y, h0, l0);
    split_pair_h(v0.z, v0.w, h1, l1);
    split_pair_h(v1.x, v1.y, h2, l2);
    split_pair_h(v1.z, v1.w, h3, l3);
    size_t o = ((size_t)mat * HH * DD + i) >> 1;
    uint32_t* ph = reinterpret_cast<uint32_t*>(g_Wh);
    uint32_t* pl = reinterpret_cast<uint32_t*>(g_Wl);
    ph[o + 0] = h0; ph[o + 1] = h1; ph[o + 2] = h2; ph[o + 3] = h3;
    pl[o + 0] = l0; pl[o + 1] = l1; pl[o + 2] = l2; pl[o + 3] = l3;
}

// ---------------------------------------------------------------------------
// proj: Q,K,V = X @ W^T, fp16 2-term: Xh*(Wh + Wl). CTA = 64 rows, 8 warps.
// X: rn f16 convert only (no split). Q out: f16 hi (scaled). K,V out: rn split.
// ---------------------------------------------------------------------------
#define PTM 64
#define PXH 0
#define PWH 9216
#define PWL 36864
#define PTOT 64512

__global__ __launch_bounds__(256) void proj_tc(const float* __restrict__ X) {
    extern __shared__ char sm[];
    const uint32_t sb = (uint32_t)__cvta_generic_to_shared(sm);
    const int tid = threadIdx.x, wid = tid >> 5, lane = tid & 31;
    const int g = lane >> 2, t = lane & 3;
    const int wm = wid >> 2, wn = wid & 3;
    const int m0 = blockIdx.x * PTM;

    float acc[3][2][2][4];
    #pragma unroll
    for (int a = 0; a < 3; a++)
        #pragma unroll
        for (int b = 0; b < 2; b++)
            #pragma unroll
            for (int c = 0; c < 2; c++)
                #pragma unroll
                for (int d = 0; d < 4; d++) acc[a][b][c][d] = 0.f;

    for (int kc = 0; kc < 16; kc++) {
        const int kbase = kc * 64;
        // X chunk: 64 rows x 64 f32 -> rn f16, hi plane only
        #pragma unroll
        for (int i = 0; i < 4; i++) {
            int id = tid + i * 256;
            int row = id >> 4, c4 = id & 15;
            float4 v = *reinterpret_cast<const float4*>(
                X + (size_t)(m0 + row) * DD + kbase + c4 * 4);
            uint32_t off = row * LDB + c4 * 8;
            *reinterpret_cast<uint32_t*>(sm + PXH + off)     = pack2h(v.x, v.y);
            *reinterpret_cast<uint32_t*>(sm + PXH + off + 4) = pack2h(v.z, v.w);
        }
        // W chunk: 192 rows x 64 f16 (hi and lo)
        #pragma unroll
        for (int i = 0; i < 12; i++) {
            int id = tid + i * 256;
            int hl = (id >= 1536);
            int rem = id - hl * 1536;
            int row = rem >> 3, c = rem & 7;
            const __half* src = hl ? g_Wl : g_Wh;
            uint4 v = *reinterpret_cast<const uint4*>(src + (size_t)row * DD + kbase + c * 8);
            *reinterpret_cast<uint4*>(sm + (hl ? PWL : PWH) + row * LDB + c * 16) = v;
        }
        __syncthreads();

        #pragma unroll
        for (int ks = 0; ks < 4; ks++) {
            uint32_t ah[2][4];
            #pragma unroll
            for (int fm = 0; fm < 2; fm++)
                ldm_x4(ah[fm], ldm_addr(sb + PXH, wm * 32 + fm * 16, ks * 16));
            #pragma unroll
            for (int mat = 0; mat < 3; mat++) {
                uint32_t bh[4], bl[4];
                ldm_x4(bh, ldm_addr_b(sb + PWH, mat * 64 + wn * 16, ks * 16));
                ldm_x4(bl, ldm_addr_b(sb + PWL, mat * 64 + wn * 16, ks * 16));
                #pragma unroll
                for (int fm = 0; fm < 2; fm++)
                    #pragma unroll
                    for (int fn = 0; fn < 2; fn++) {
                        mma_f16(acc[mat][fm][fn], ah[fm], &bh[fn * 2]);
                        mma_f16(acc[mat][fm][fn], ah[fm], &bl[fn * 2]);
                    }
            }
        }
        __syncthreads();
    }

    // epilogue: Q -> f16 hi (rn) with log2e/32 scale; K,V -> rn split
    {
        const float scl = 1.44269504f / 32.0f;
        #pragma unroll
        for (int fm = 0; fm < 2; fm++)
            #pragma unroll
            for (int fn = 0; fn < 2; fn++) {
                const float* c = acc[0][fm][fn];
                int r0 = m0 + wm * 32 + fm * 16 + g;
                int col = wn * 16 + fn * 8 + t * 2;
                reinterpret_cast<uint32_t*>(g_Qh)[((size_t)r0 * HH + col) >> 1] =
                    pack2h(c[0] * scl, c[1] * scl);
                reinterpret_cast<uint32_t*>(g_Qh)[((size_t)(r0 + 8) * HH + col) >> 1] =
                    pack2h(c[2] * scl, c[3] * scl);
            }
    }
    #pragma unroll
    for (int mat = 1; mat < 3; mat++) {
        __half* gh = (mat == 1) ? g_Kh : g_Vh;
        __half* gl = (mat == 1) ? g_Kl : g_Vl;
        #pragma unroll
        for (int fm = 0; fm < 2; fm++)
            #pragma unroll
            for (int fn = 0; fn < 2; fn++) {
                const float* c = acc[mat][fm][fn];
                int r0 = m0 + wm * 32 + fm * 16 + g;
                int col = wn * 16 + fn * 8 + t * 2;
                uint32_t h, l;
                split_pair_h(c[0], c[1], h, l);
                reinterpret_cast<uint32_t*>(gh)[((size_t)r0 * HH + col) >> 1] = h;
                reinterpret_cast<uint32_t*>(gl)[((size_t)r0 * HH + col) >> 1] = l;
                split_pair_h(c[2], c[3], h, l);
                reinterpret_cast<uint32_t*>(gh)[((size_t)(r0 + 8) * HH + col) >> 1] = h;
                reinterpret_cast<uint32_t*>(gl)[((size_t)(r0 + 8) * HH + col) >> 1] = l;
            }
    }
}

// ---------------------------------------------------------------------------
// attn: flash attention (fp16), no-max softmax, register P (hi-only),
// 2-stage cp.async K/V pipeline. 256 CTAs balanced, warps 4 qw x 2 kw.
// S = Qh*(Kh+Kl);  O += Ph*(Vh+Vl).
// ---------------------------------------------------------------------------
#define AQ    0
#define PLANE 9216
#define ABUF  9216
#define STG   (4 * PLANE)
#define ALR   (ABUF + 2 * STG)
#define ATOT  (ALR + 512)

__global__ __launch_bounds__(256, 2) void attn_tc(float* __restrict__ Outp) {
    extern __shared__ char sm[];
    const uint32_t sb = (uint32_t)__cvta_generic_to_shared(sm);
    const int tid = threadIdx.x, wid = tid >> 5, lane = tid & 31;
    const int g = lane >> 2, t = lane & 3;
    const int qw = wid >> 1, kw = wid & 1;

    const int bid = blockIdx.x;
    int qt, b;
    if (bid < 108)      { qt = bid % 27;            b = bid / 27; }
    else if (bid < 148) { int s = bid - 108;        qt = 27 + (s >> 3); b = s & 7; }
    else                { int p = bid - 148;        qt = 26 - (p % 27); b = (p / 27) + 4; }

    const int q0 = qt * 64;
    const size_t base = (size_t)b * SS;

    {
        #pragma unroll
        for (int i = 0; i < 8; i++) {
            int id = tid + i * 256;
            int plane = id >> 9, rem = id & 511;
            int row = rem >> 3, c = rem & 7;
            const __half* src =
                (plane == 0) ? g_Kh : ((plane == 1) ? g_Kl : ((plane == 2) ? g_Vh : g_Vl));
            cp16(sb + ABUF + plane * PLANE + row * LDB + c * 16,
                 src + (base + row) * HH + c * 8);
        }
    }
    CP_COMMIT();

    #pragma unroll
    for (int i = 0; i < 2; i++) {
        int id = tid + i * 256;
        int row = id >> 3, c = id & 7;
        *reinterpret_cast<uint4*>(sm + AQ + row * LDB + c * 16) =
            *reinterpret_cast<const uint4*>(g_Qh + (base + q0 + row) * HH + c * 8);
    }

    float o[8][4];
    #pragma unroll
    for (int i = 0; i < 8; i++)
        #pragma unroll
        for (int j = 0; j < 4; j++) o[i][j] = 0.f;
    float lsum0 = 0.f, lsum1 = 0.f;

    for (int kt = 0; kt <= qt; kt++) {
        const int k0 = kt * 64;
        CP_WAIT0();
        __syncthreads();

        if (kt < qt) {
            const int kn = k0 + 64;
            const uint32_t dstg = sb + ABUF + ((kt + 1) & 1) * STG;
            #pragma unroll
            for (int i = 0; i < 8; i++) {
                int id = tid + i * 256;
                int plane = id >> 9, rem = id & 511;
                int row = rem >> 3, c = rem & 7;
                const __half* src =
                    (plane == 0) ? g_Kh : ((plane == 1) ? g_Kl : ((plane == 2) ? g_Vh : g_Vl));
                cp16(dstg + plane * PLANE + row * LDB + c * 16,
                     src + (base + kn + row) * HH + c * 8);
            }
        }
        CP_COMMIT();

        const uint32_t stg = sb + ABUF + (kt & 1) * STG;
        const uint32_t sKH = stg, sKL = stg + PLANE, sVH = stg + 2 * PLANE, sVL = stg + 3 * PLANE;

        float s[4][4];
        #pragma unroll
        for (int i = 0; i < 4; i++)
            #pragma unroll
            for (int j = 0; j < 4; j++) s[i][j] = 0.f;

        #pragma unroll
        for (int hs = 0; hs < 4; hs++) {
            uint32_t ah[4], bh[4], bl[4], bh2[4], bl2[4];
            ldm_x4(ah, ldm_addr(sb + AQ, qw * 16, hs * 16));
            ldm_x4(bh,  ldm_addr_b(sKH, kw * 32,      hs * 16));
            ldm_x4(bl,  ldm_addr_b(sKL, kw * 32,      hs * 16));
            ldm_x4(bh2, ldm_addr_b(sKH, kw * 32 + 16, hs * 16));
            ldm_x4(bl2, ldm_addr_b(sKL, kw * 32 + 16, hs * 16));
            #pragma unroll
            for (int fn = 0; fn < 2; fn++) {
                mma_f16(s[fn],     ah, &bh[fn * 2]);
                mma_f16(s[fn],     ah, &bl[fn * 2]);
                mma_f16(s[2 + fn], ah, &bh2[fn * 2]);
                mma_f16(s[2 + fn], ah, &bl2[fn * 2]);
            }
        }

        if (kt == qt) {
            #pragma unroll
            for (int f = 0; f < 4; f++) {
                int kg = k0 + kw * 32 + f * 8 + t * 2;
                int qg0 = q0 + qw * 16 + g, qg1 = qg0 + 8;
                if (kg     > qg0) s[f][0] = -200.f;
                if (kg + 1 > qg0) s[f][1] = -200.f;
                if (kg     > qg1) s[f][2] = -200.f;
                if (kg + 1 > qg1) s[f][3] = -200.f;
            }
        }

        // P = 2^{S'}; row sums; P -> fp16 rn A-fragments (hi only)
        uint32_t pah[2][4];
        #pragma unroll
        for (int ks2 = 0; ks2 < 2; ks2++) {
            #pragma unroll
            for (int ff = 0; ff < 2; ff++) {
                const int f = ks2 * 2 + ff;
                float p0 = fast_exp2(s[f][0]);
                float p1 = fast_exp2(s[f][1]);
                float p2 = fast_exp2(s[f][2]);
                float p3 = fast_exp2(s[f][3]);
                lsum0 += p0 + p1;
                lsum1 += p2 + p3;
                pah[ks2][ff * 2]     = pack2h(p0, p1);
                pah[ks2][ff * 2 + 1] = pack2h(p2, p3);
            }
        }

        // O += Ph (Vh + Vl) over this warp's k-half, all 64 h columns
        #pragma unroll
        for (int ks2 = 0; ks2 < 2; ks2++) {
            uint32_t vh[4][4], vl[4][4];
            #pragma unroll
            for (int c = 0; c < 4; c++) {
                ldm_x4_t(vh[c], ldm_addr(sVH, kw * 32 + ks2 * 16, c * 16));
                ldm_x4_t(vl[c], ldm_addr(sVL, kw * 32 + ks2 * 16, c * 16));
            }
            #pragma unroll
            for (int j = 0; j < 8; j++) {
                mma_f16(o[j], pah[ks2], &vh[j >> 1][(j & 1) * 2]);
                mma_f16(o[j], pah[ks2], &vl[j >> 1][(j & 1) * 2]);
            }
        }
    }
    __syncthreads();

    lsum0 += __shfl_xor_sync(0xFFFFFFFFu, lsum0, 1);
    lsum0 += __shfl_xor_sync(0xFFFFFFFFu, lsum0, 2);
    lsum1 += __shfl_xor_sync(0xFFFFFFFFu, lsum1, 1);
    lsum1 += __shfl_xor_sync(0xFFFFFFFFu, lsum1, 2);
    float* lred = reinterpret_cast<float*>(sm + ALR);
    if (t == 0) {
        lred[(qw * 2 + kw) * 16 + g]     = lsum0;
        lred[(qw * 2 + kw) * 16 + 8 + g] = lsum1;
    }
    float* ored = reinterpret_cast<float*>(sm);
    if (kw == 1) {
        #pragma unroll
        for (int j = 0; j < 8; j++) {
            int col = j * 8 + t * 2;
            *reinterpret_cast<float2*>(&ored[(qw * 16 + g) * 64 + col]) =
                make_float2(o[j][0], o[j][1]);
            *reinterpret_cast<float2*>(&ored[(qw * 16 + g + 8) * 64 + col]) =
                make_float2(o[j][2], o[j][3]);
        }
    }
    __syncthreads();

    if (kw == 0) {
        float inv0 = 1.f / (lred[(qw * 2) * 16 + g]     + lred[(qw * 2 + 1) * 16 + g]);
        float inv1 = 1.f / (lred[(qw * 2) * 16 + 8 + g] + lred[(qw * 2 + 1) * 16 + 8 + g]);
        #pragma unroll
        for (int j = 0; j < 8; j++) {
            int col = j * 8 + t * 2;
            float2 a0 = *reinterpret_cast<float2*>(&ored[(qw * 16 + g) * 64 + col]);
            float2 a1 = *reinterpret_cast<float2*>(&ored[(qw * 16 + g + 8) * 64 + col]);
            size_t r0 = (base + q0 + qw * 16 + g) * HH + col;
            *reinterpret_cast<float2*>(Outp + r0) =
                make_float2((o[j][0] + a0.x) * inv0, (o[j][1] + a0.y) * inv0);
            *reinterpret_cast<float2*>(Outp + r0 + 8 * HH) =
                make_float2((o[j][2] + a1.x) * inv1, (o[j][3] + a1.y) * inv1);
        }
    }
}

// ---------------------------------------------------------------------------
extern "C" void kernel_launch(void* const* d_in, const int* in_sizes, int n_in,
                              void* d_out, int out_size)
{
    const float* X  = (const float*)d_in[0];
    const float* Wk = (const float*)d_in[1];
    const float* Wq = (const float*)d_in[2];
    const float* Wv = (const float*)d_in[3];
    float* Out = (float*)d_out;
    (void)in_sizes; (void)n_in; (void)out_size;

    cudaFuncSetAttribute(proj_tc, cudaFuncAttributeMaxDynamicSharedMemorySize, PTOT);
    cudaFuncSetAttribute(attn_tc, cudaFuncAttributeMaxDynamicSharedMemorySize, ATOT);

    prep_w<<<dim3(32, 3), 256>>>(Wq, Wk, Wv);
    proj_tc<<<MM / PTM, 256, PTOT>>>(X);
    attn_tc<<<256, 256, ATOT>>>(Out);
}

// round 8
// speedup vs baseline: 1.6656x; 1.3424x over previous
#include <cuda_runtime.h>
#include <cuda_fp16.h>
#include <cstdint>

#define BB 8
#define SS 2048
#define DD 1024
#define HH 64
#define MM (BB*SS)

// Scratch (fp16): Q pre-scaled by log2e/32; K,V hi-only
__device__ __align__(16) __half g_Qh[MM*HH];
__device__ __align__(16) __half g_Kh[MM*HH];
__device__ __align__(16) __half g_Vh[MM*HH];
// W split: [3][64][1024], mat order {Q,K,V}
__device__ __align__(16) __half g_Wh[3*HH*DD];
__device__ __align__(16) __half g_Wl[3*HH*DD];

// ---------------------------------------------------------------------------
// helpers
// ---------------------------------------------------------------------------
__device__ __forceinline__ uint32_t pack2h(float lo, float hi) {
    uint32_t r;
    asm("cvt.rn.f16x2.f32 %0, %1, %2;" : "=r"(r) : "f"(hi), "f"(lo));
    return r;
}
__device__ __forceinline__ void split_pair_h(float x0, float x1, uint32_t& h, uint32_t& l) {
    float h0 = __half2float(__float2half_rn(x0));
    float h1 = __half2float(__float2half_rn(x1));
    h = pack2h(h0, h1);
    l = pack2h(x0 - h0, x1 - h1);
}

__device__ __forceinline__ void ldm_x4(uint32_t* r, uint32_t addr) {
    asm volatile("ldmatrix.sync.aligned.m8n8.x4.shared.b16 {%0,%1,%2,%3}, [%4];"
                 : "=r"(r[0]), "=r"(r[1]), "=r"(r[2]), "=r"(r[3]) : "r"(addr));
}
__device__ __forceinline__ void ldm_x4_t(uint32_t* r, uint32_t addr) {
    asm volatile("ldmatrix.sync.aligned.m8n8.x4.trans.shared.b16 {%0,%1,%2,%3}, [%4];"
                 : "=r"(r[0]), "=r"(r[1]), "=r"(r[2]), "=r"(r[3]) : "r"(addr));
}

__device__ __forceinline__ void cp16(uint32_t dst, const void* src) {
    asm volatile("cp.async.cg.shared.global [%0], [%1], 16;"
                 :: "r"(dst), "l"(src) : "memory");
}
#define CP_COMMIT() asm volatile("cp.async.commit_group;" ::: "memory")
#define CP_WAIT0()  asm volatile("cp.async.wait_group 0;" ::: "memory")

// smem fp16 tiles: row stride 144 bytes (72 halves) -> ldmatrix conflict-free
#define LDB 144

__device__ __forceinline__ uint32_t ldm_addr(uint32_t base, int row0, int col0) {
    int l = threadIdx.x & 31;
    int r = row0 + (l & 7) + ((l >> 3) & 1) * 8;
    int c = col0 + (l >> 4) * 8;
    return base + r * LDB + c * 2;
}
__device__ __forceinline__ uint32_t ldm_addr_b(uint32_t base, int row0, int col0) {
    int l = threadIdx.x & 31;
    int r = row0 + (l & 7) + (l >> 4) * 8;
    int c = col0 + ((l >> 3) & 1) * 8;
    return base + r * LDB + c * 2;
}

__device__ __forceinline__ void mma_f16(float* d, const uint32_t* a, const uint32_t* b) {
    asm volatile(
        "mma.sync.aligned.m16n8k16.row.col.f32.f16.f16.f32 "
        "{%0,%1,%2,%3}, {%4,%5,%6,%7}, {%8,%9}, {%0,%1,%2,%3};"
        : "+f"(d[0]), "+f"(d[1]), "+f"(d[2]), "+f"(d[3])
        : "r"(a[0]), "r"(a[1]), "r"(a[2]), "r"(a[3]), "r"(b[0]), "r"(b[1]));
}

// 2^x via magic-round + deg-4 Taylor; clamps below -126.
__device__ __forceinline__ float fast_exp2(float x) {
    x = fmaxf(x, -126.0f);
    float r = x + 12582912.0f;
    int ik = __float_as_int(r) - 0x4B400000;
    float f = x - (r - 12582912.0f);
    float p = fmaf(0.0096180f, f, 0.0555041f);
    p = fmaf(p, f, 0.2402265f);
    p = fmaf(p, f, 0.6931472f);
    p = fmaf(p, f, 1.0f);
    return __int_as_float(__float_as_int(p) + (ik << 23));
}

// ---------------------------------------------------------------------------
// prep_w: split weights into fp16 hi/lo (rn). grid (32,3), 8 f32/thread.
// ---------------------------------------------------------------------------
__global__ __launch_bounds__(256) void prep_w(const float* __restrict__ Wq,
                                              const float* __restrict__ Wk,
                                              const float* __restrict__ Wv) {
    int mat = blockIdx.y;
    const float* W = (mat == 0) ? Wq : ((mat == 1) ? Wk : Wv);
    int i = blockIdx.x * 2048 + threadIdx.x * 8;
    float4 v0 = *reinterpret_cast<const float4*>(W + i);
    float4 v1 = *reinterpret_cast<const float4*>(W + i + 4);
    uint32_t h0, l0, h1, l1, h2, l2, h3, l3;
    split_pair_h(v0.x, v0.y, h0, l0);
    split_pair_h(v0.z, v0.w, h1, l1);
    split_pair_h(v1.x, v1.y, h2, l2);
    split_pair_h(v1.z, v1.w, h3, l3);
    size_t o = ((size_t)mat * HH * DD + i) >> 1;
    uint32_t* ph = reinterpret_cast<uint32_t*>(g_Wh);
    uint32_t* pl = reinterpret_cast<uint32_t*>(g_Wl);
    ph[o + 0] = h0; ph[o + 1] = h1; ph[o + 2] = h2; ph[o + 3] = h3;
    pl[o + 0] = l0; pl[o + 1] = l1; pl[o + 2] = l2; pl[o + 3] = l3;
}

// ---------------------------------------------------------------------------
// proj: Q,V = Xh*(Wh+Wl) 2-term; K = Xh*Wh 1-term. CTA = 64 rows, 8 warps.
// Outputs fp16 hi-only (Q scaled by log2e/32).
// ---------------------------------------------------------------------------
#define PTM 64
#define PXH 0
#define PWH 9216
#define PWL 36864
#define PTOT 64512

__global__ __launch_bounds__(256) void proj_tc(const float* __restrict__ X) {
    extern __shared__ char sm[];
    const uint32_t sb = (uint32_t)__cvta_generic_to_shared(sm);
    const int tid = threadIdx.x, wid = tid >> 5, lane = tid & 31;
    const int g = lane >> 2, t = lane & 3;
    const int wm = wid >> 2, wn = wid & 3;
    const int m0 = blockIdx.x * PTM;

    float acc[3][2][2][4];
    #pragma unroll
    for (int a = 0; a < 3; a++)
        #pragma unroll
        for (int b = 0; b < 2; b++)
            #pragma unroll
            for (int c = 0; c < 2; c++)
                #pragma unroll
                for (int d = 0; d < 4; d++) acc[a][b][c][d] = 0.f;

    for (int kc = 0; kc < 16; kc++) {
        const int kbase = kc * 64;
        // X chunk: 64 rows x 64 f32 -> rn f16
        #pragma unroll
        for (int i = 0; i < 4; i++) {
            int id = tid + i * 256;
            int row = id >> 4, c4 = id & 15;
            float4 v = *reinterpret_cast<const float4*>(
                X + (size_t)(m0 + row) * DD + kbase + c4 * 4);
            uint32_t off = row * LDB + c4 * 8;
            *reinterpret_cast<uint32_t*>(sm + PXH + off)     = pack2h(v.x, v.y);
            *reinterpret_cast<uint32_t*>(sm + PXH + off + 4) = pack2h(v.z, v.w);
        }
        // W chunk: 192 rows x 64 f16 (hi and lo)
        #pragma unroll
        for (int i = 0; i < 12; i++) {
            int id = tid + i * 256;
            int hl = (id >= 1536);
            int rem = id - hl * 1536;
            int row = rem >> 3, c = rem & 7;
            const __half* src = hl ? g_Wl : g_Wh;
            uint4 v = *reinterpret_cast<const uint4*>(src + (size_t)row * DD + kbase + c * 8);
            *reinterpret_cast<uint4*>(sm + (hl ? PWL : PWH) + row * LDB + c * 16) = v;
        }
        __syncthreads();

        #pragma unroll
        for (int ks = 0; ks < 4; ks++) {
            uint32_t ah[2][4];
            #pragma unroll
            for (int fm = 0; fm < 2; fm++)
                ldm_x4(ah[fm], ldm_addr(sb + PXH, wm * 32 + fm * 16, ks * 16));
            #pragma unroll
            for (int mat = 0; mat < 3; mat++) {
                uint32_t bh[4], bl[4];
                ldm_x4(bh, ldm_addr_b(sb + PWH, mat * 64 + wn * 16, ks * 16));
                if (mat != 1) ldm_x4(bl, ldm_addr_b(sb + PWL, mat * 64 + wn * 16, ks * 16));
                #pragma unroll
                for (int fm = 0; fm < 2; fm++)
                    #pragma unroll
                    for (int fn = 0; fn < 2; fn++) {
                        mma_f16(acc[mat][fm][fn], ah[fm], &bh[fn * 2]);
                        if (mat != 1) mma_f16(acc[mat][fm][fn], ah[fm], &bl[fn * 2]);
                    }
            }
        }
        __syncthreads();
    }

    // epilogue: all outputs fp16 hi-only; Q scaled by log2e/32
    #pragma unroll
    for (int mat = 0; mat < 3; mat++) {
        __half* gh = (mat == 0) ? g_Qh : ((mat == 1) ? g_Kh : g_Vh);
        const float scl = (mat == 0) ? (1.44269504f / 32.0f) : 1.0f;
        #pragma unroll
        for (int fm = 0; fm < 2; fm++)
            #pragma unroll
            for (int fn = 0; fn < 2; fn++) {
                const float* c = acc[mat][fm][fn];
                int r0 = m0 + wm * 32 + fm * 16 + g;
                int col = wn * 16 + fn * 8 + t * 2;
                reinterpret_cast<uint32_t*>(gh)[((size_t)r0 * HH + col) >> 1] =
                    pack2h(c[0] * scl, c[1] * scl);
                reinterpret_cast<uint32_t*>(gh)[((size_t)(r0 + 8) * HH + col) >> 1] =
                    pack2h(c[2] * scl, c[3] * scl);
            }
    }
}

// ---------------------------------------------------------------------------
// attn: flash attention (fp16 hi-only), no-max softmax, register P,
// 2-stage cp.async K/V pipeline (2 planes/stage). 256 CTAs balanced.
// ---------------------------------------------------------------------------
#define AQ    0
#define PLANE 9216
#define ABUF  9216
#define STG   (2 * PLANE)       // Kh, Vh
#define ALR   (ABUF + 2 * STG)  // 46080
#define ATOT  (ALR + 512)       // 46592

__global__ __launch_bounds__(256, 2) void attn_tc(float* __restrict__ Outp) {
    extern __shared__ char sm[];
    const uint32_t sb = (uint32_t)__cvta_generic_to_shared(sm);
    const int tid = threadIdx.x, wid = tid >> 5, lane = tid & 31;
    const int g = lane >> 2, t = lane & 3;
    const int qw = wid >> 1, kw = wid & 1;

    const int bid = blockIdx.x;
    int qt, b;
    if (bid < 108)      { qt = bid % 27;            b = bid / 27; }
    else if (bid < 148) { int s = bid - 108;        qt = 27 + (s >> 3); b = s & 7; }
    else                { int p = bid - 148;        qt = 26 - (p % 27); b = (p / 27) + 4; }

    const int q0 = qt * 64;
    const size_t base = (size_t)b * SS;

    // prefetch tile 0 (2 planes x 512 x 16B)
    #pragma unroll
    for (int i = 0; i < 4; i++) {
        int id = tid + i * 256;
        int plane = id >> 9, rem = id & 511;
        int row = rem >> 3, c = rem & 7;
        const __half* src = (plane == 0) ? g_Kh : g_Vh;
        cp16(sb + ABUF + plane * PLANE + row * LDB + c * 16,
             src + (base + row) * HH + c * 8);
    }
    CP_COMMIT();

    #pragma unroll
    for (int i = 0; i < 2; i++) {
        int id = tid + i * 256;
        int row = id >> 3, c = id & 7;
        *reinterpret_cast<uint4*>(sm + AQ + row * LDB + c * 16) =
            *reinterpret_cast<const uint4*>(g_Qh + (base + q0 + row) * HH + c * 8);
    }

    float o[8][4];
    #pragma unroll
    for (int i = 0; i < 8; i++)
        #pragma unroll
        for (int j = 0; j < 4; j++) o[i][j] = 0.f;
    float lsum0 = 0.f, lsum1 = 0.f;

    for (int kt = 0; kt <= qt; kt++) {
        const int k0 = kt * 64;
        CP_WAIT0();
        __syncthreads();

        if (kt < qt) {
            const int kn = k0 + 64;
            const uint32_t dstg = sb + ABUF + ((kt + 1) & 1) * STG;
            #pragma unroll
            for (int i = 0; i < 4; i++) {
                int id = tid + i * 256;
                int plane = id >> 9, rem = id & 511;
                int row = rem >> 3, c = rem & 7;
                const __half* src = (plane == 0) ? g_Kh : g_Vh;
                cp16(dstg + plane * PLANE + row * LDB + c * 16,
                     src + (base + kn + row) * HH + c * 8);
            }
        }
        CP_COMMIT();

        const uint32_t stg = sb + ABUF + (kt & 1) * STG;
        const uint32_t sKH = stg, sVH = stg + PLANE;

        // S' = Qh Kh^T (log2 domain)
        float s[4][4];
        #pragma unroll
        for (int i = 0; i < 4; i++)
            #pragma unroll
            for (int j = 0; j < 4; j++) s[i][j] = 0.f;

        #pragma unroll
        for (int hs = 0; hs < 4; hs++) {
            uint32_t ah[4], bh[4], bh2[4];
            ldm_x4(ah, ldm_addr(sb + AQ, qw * 16, hs * 16));
            ldm_x4(bh,  ldm_addr_b(sKH, kw * 32,      hs * 16));
            ldm_x4(bh2, ldm_addr_b(sKH, kw * 32 + 16, hs * 16));
            #pragma unroll
            for (int fn = 0; fn < 2; fn++) {
                mma_f16(s[fn],     ah, &bh[fn * 2]);
                mma_f16(s[2 + fn], ah, &bh2[fn * 2]);
            }
        }

        if (kt == qt) {
            #pragma unroll
            for (int f = 0; f < 4; f++) {
                int kg = k0 + kw * 32 + f * 8 + t * 2;
                int qg0 = q0 + qw * 16 + g, qg1 = qg0 + 8;
                if (kg     > qg0) s[f][0] = -200.f;
                if (kg + 1 > qg0) s[f][1] = -200.f;
                if (kg     > qg1) s[f][2] = -200.f;
                if (kg + 1 > qg1) s[f][3] = -200.f;
            }
        }

        // P = 2^{S'}; row sums; P -> fp16 rn A-fragments
        uint32_t pah[2][4];
        #pragma unroll
        for (int ks2 = 0; ks2 < 2; ks2++) {
            #pragma unroll
            for (int ff = 0; ff < 2; ff++) {
                const int f = ks2 * 2 + ff;
                float p0 = fast_exp2(s[f][0]);
                float p1 = fast_exp2(s[f][1]);
                float p2 = fast_exp2(s[f][2]);
                float p3 = fast_exp2(s[f][3]);
                lsum0 += p0 + p1;
                lsum1 += p2 + p3;
                pah[ks2][ff * 2]     = pack2h(p0, p1);
                pah[ks2][ff * 2 + 1] = pack2h(p2, p3);
            }
        }

        // O += Ph Vh over this warp's k-half, all 64 h columns
        #pragma unroll
        for (int ks2 = 0; ks2 < 2; ks2++) {
            uint32_t vh[4][4];
            #pragma unroll
            for (int c = 0; c < 4; c++)
                ldm_x4_t(vh[c], ldm_addr(sVH, kw * 32 + ks2 * 16, c * 16));
            #pragma unroll
            for (int j = 0; j < 8; j++)
                mma_f16(o[j], pah[ks2], &vh[j >> 1][(j & 1) * 2]);
        }
    }
    __syncthreads();

    lsum0 += __shfl_xor_sync(0xFFFFFFFFu, lsum0, 1);
    lsum0 += __shfl_xor_sync(0xFFFFFFFFu, lsum0, 2);
    lsum1 += __shfl_xor_sync(0xFFFFFFFFu, lsum1, 1);
    lsum1 += __shfl_xor_sync(0xFFFFFFFFu, lsum1, 2);
    float* lred = reinterpret_cast<float*>(sm + ALR);
    if (t == 0) {
        lred[(qw * 2 + kw) * 16 + g]     = lsum0;
        lred[(qw * 2 + kw) * 16 + 8 + g] = lsum1;
    }
    float* ored = reinterpret_cast<float*>(sm);
    if (kw == 1) {
        #pragma unroll
        for (int j = 0; j < 8; j++) {
            int col = j * 8 + t * 2;
            *reinterpret_cast<float2*>(&ored[(qw * 16 + g) * 64 + col]) =
                make_float2(o[j][0], o[j][1]);
            *reinterpret_cast<float2*>(&ored[(qw * 16 + g + 8) * 64 + col]) =
                make_float2(o[j][2], o[j][3]);
        }
    }
    __syncthreads();

    if (kw == 0) {
        float inv0 = 1.f / (lred[(qw * 2) * 16 + g]     + lred[(qw * 2 + 1) * 16 + g]);
        float inv1 = 1.f / (lred[(qw * 2) * 16 + 8 + g] + lred[(qw * 2 + 1) * 16 + 8 + g]);
        #pragma unroll
        for (int j = 0; j < 8; j++) {
            int col = j * 8 + t * 2;
            float2 a0 = *reinterpret_cast<float2*>(&ored[(qw * 16 + g) * 64 + col]);
            float2 a1 = *reinterpret_cast<float2*>(&ored[(qw * 16 + g + 8) * 64 + col]);
            size_t r0 = (base + q0 + qw * 16 + g) * HH + col;
            *reinterpret_cast<float2*>(Outp + r0) =
                make_float2((o[j][0] + a0.x) * inv0, (o[j][1] + a0.y) * inv0);
            *reinterpret_cast<float2*>(Outp + r0 + 8 * HH) =
                make_float2((o[j][2] + a1.x) * inv1, (o[j][3] + a1.y) * inv1);
        }
    }
}

// ---------------------------------------------------------------------------
extern "C" void kernel_launch(void* const* d_in, const int* in_sizes, int n_in,
                              void* d_out, int out_size)
{
    const float* X  = (const float*)d_in[0];
    const float* Wk = (const float*)d_in[1];
    const float* Wq = (const float*)d_in[2];
    const float* Wv = (const float*)d_in[3];
    float* Out = (float*)d_out;
    (void)in_sizes; (void)n_in; (void)out_size;

    cudaFuncSetAttribute(proj_tc, cudaFuncAttributeMaxDynamicSharedMemorySize, PTOT);
    cudaFuncSetAttribute(attn_tc, cudaFuncAttributeMaxDynamicSharedMemorySize, ATOT);

    prep_w<<<dim3(32, 3), 256>>>(Wq, Wk, Wv);
    proj_tc<<<MM / PTM, 256, PTOT>>>(X);
    attn_tc<<<256, 256, ATOT>>>(Out);
}

// round 9
// speedup vs baseline: 1.9792x; 1.1883x over previous
#include <cuda_runtime.h>
#include <cuda_fp16.h>
#include <cstdint>

#define BB 8
#define SS 2048
#define DD 1024
#define HH 64
#define MM (BB*SS)

// Scratch (fp16): Q pre-scaled by log2e/32; K,V hi-only
__device__ __align__(16) __half g_Qh[MM*HH];
__device__ __align__(16) __half g_Kh[MM*HH];
__device__ __align__(16) __half g_Vh[MM*HH];
// W hi (fp16 rn): [3][64][1024], mat order {Q,K,V}
__device__ __align__(16) __half g_Wh[3*HH*DD];

// ---------------------------------------------------------------------------
// helpers
// ---------------------------------------------------------------------------
__device__ __forceinline__ uint32_t pack2h(float lo, float hi) {
    uint32_t r;
    asm("cvt.rn.f16x2.f32 %0, %1, %2;" : "=r"(r) : "f"(hi), "f"(lo));
    return r;
}

__device__ __forceinline__ void ldm_x4(uint32_t* r, uint32_t addr) {
    asm volatile("ldmatrix.sync.aligned.m8n8.x4.shared.b16 {%0,%1,%2,%3}, [%4];"
                 : "=r"(r[0]), "=r"(r[1]), "=r"(r[2]), "=r"(r[3]) : "r"(addr));
}
__device__ __forceinline__ void ldm_x4_t(uint32_t* r, uint32_t addr) {
    asm volatile("ldmatrix.sync.aligned.m8n8.x4.trans.shared.b16 {%0,%1,%2,%3}, [%4];"
                 : "=r"(r[0]), "=r"(r[1]), "=r"(r[2]), "=r"(r[3]) : "r"(addr));
}

__device__ __forceinline__ void cp16(uint32_t dst, const void* src) {
    asm volatile("cp.async.cg.shared.global [%0], [%1], 16;"
                 :: "r"(dst), "l"(src) : "memory");
}
#define CP_COMMIT() asm volatile("cp.async.commit_group;" ::: "memory")
#define CP_WAIT0()  asm volatile("cp.async.wait_group 0;" ::: "memory")

// smem fp16 tiles: row stride 144 bytes (72 halves) -> ldmatrix conflict-free
#define LDB 144

__device__ __forceinline__ uint32_t ldm_addr(uint32_t base, int row0, int col0) {
    int l = threadIdx.x & 31;
    int r = row0 + (l & 7) + ((l >> 3) & 1) * 8;
    int c = col0 + (l >> 4) * 8;
    return base + r * LDB + c * 2;
}
__device__ __forceinline__ uint32_t ldm_addr_b(uint32_t base, int row0, int col0) {
    int l = threadIdx.x & 31;
    int r = row0 + (l & 7) + (l >> 4) * 8;
    int c = col0 + ((l >> 3) & 1) * 8;
    return base + r * LDB + c * 2;
}

__device__ __forceinline__ void mma_f16(float* d, const uint32_t* a, const uint32_t* b) {
    asm volatile(
        "mma.sync.aligned.m16n8k16.row.col.f32.f16.f16.f32 "
        "{%0,%1,%2,%3}, {%4,%5,%6,%7}, {%8,%9}, {%0,%1,%2,%3};"
        : "+f"(d[0]), "+f"(d[1]), "+f"(d[2]), "+f"(d[3])
        : "r"(a[0]), "r"(a[1]), "r"(a[2]), "r"(a[3]), "r"(b[0]), "r"(b[1]));
}

// 2^x via magic-round + deg-4 Taylor; clamps below -126.
__device__ __forceinline__ float fast_exp2(float x) {
    x = fmaxf(x, -126.0f);
    float r = x + 12582912.0f;
    int ik = __float_as_int(r) - 0x4B400000;
    float f = x - (r - 12582912.0f);
    float p = fmaf(0.0096180f, f, 0.0555041f);
    p = fmaf(p, f, 0.2402265f);
    p = fmaf(p, f, 0.6931472f);
    p = fmaf(p, f, 1.0f);
    return __int_as_float(__float_as_int(p) + (ik << 23));
}

// ---------------------------------------------------------------------------
// prep_w: convert weights to fp16 (rn), hi only. grid (32,3), 8 f32/thread.
// ---------------------------------------------------------------------------
__global__ __launch_bounds__(256) void prep_w(const float* __restrict__ Wq,
                                              const float* __restrict__ Wk,
                                              const float* __restrict__ Wv) {
    int mat = blockIdx.y;
    const float* W = (mat == 0) ? Wq : ((mat == 1) ? Wk : Wv);
    int i = blockIdx.x * 2048 + threadIdx.x * 8;
    float4 v0 = *reinterpret_cast<const float4*>(W + i);
    float4 v1 = *reinterpret_cast<const float4*>(W + i + 4);
    size_t o = ((size_t)mat * HH * DD + i) >> 1;
    uint32_t* ph = reinterpret_cast<uint32_t*>(g_Wh);
    ph[o + 0] = pack2h(v0.x, v0.y);
    ph[o + 1] = pack2h(v0.z, v0.w);
    ph[o + 2] = pack2h(v1.x, v1.y);
    ph[o + 3] = pack2h(v1.z, v1.w);
}

// ---------------------------------------------------------------------------
// proj: Q,K,V = Xh @ Wh^T (1-term fp16). CTA = 64 rows, 8 warps (2m x 4n).
// Outputs fp16 hi-only (Q scaled by log2e/32).
// ---------------------------------------------------------------------------
#define PTM 64
#define PXH 0
#define PWH 9216
#define PTOT 36864

__global__ __launch_bounds__(256) void proj_tc(const float* __restrict__ X) {
    extern __shared__ char sm[];
    const uint32_t sb = (uint32_t)__cvta_generic_to_shared(sm);
    const int tid = threadIdx.x, wid = tid >> 5, lane = tid & 31;
    const int g = lane >> 2, t = lane & 3;
    const int wm = wid >> 2, wn = wid & 3;
    const int m0 = blockIdx.x * PTM;

    float acc[3][2][2][4];
    #pragma unroll
    for (int a = 0; a < 3; a++)
        #pragma unroll
        for (int b = 0; b < 2; b++)
            #pragma unroll
            for (int c = 0; c < 2; c++)
                #pragma unroll
                for (int d = 0; d < 4; d++) acc[a][b][c][d] = 0.f;

    for (int kc = 0; kc < 16; kc++) {
        const int kbase = kc * 64;
        // X chunk: 64 rows x 64 f32 -> rn f16
        #pragma unroll
        for (int i = 0; i < 4; i++) {
            int id = tid + i * 256;
            int row = id >> 4, c4 = id & 15;
            float4 v = *reinterpret_cast<const float4*>(
                X + (size_t)(m0 + row) * DD + kbase + c4 * 4);
            uint32_t off = row * LDB + c4 * 8;
            *reinterpret_cast<uint32_t*>(sm + PXH + off)     = pack2h(v.x, v.y);
            *reinterpret_cast<uint32_t*>(sm + PXH + off + 4) = pack2h(v.z, v.w);
        }
        // W chunk: 192 rows x 64 f16
        #pragma unroll
        for (int i = 0; i < 6; i++) {
            int id = tid + i * 256;
            int row = id >> 3, c = id & 7;
            uint4 v = *reinterpret_cast<const uint4*>(g_Wh + (size_t)row * DD + kbase + c * 8);
            *reinterpret_cast<uint4*>(sm + PWH + row * LDB + c * 16) = v;
        }
        __syncthreads();

        #pragma unroll
        for (int ks = 0; ks < 4; ks++) {
            uint32_t ah[2][4];
            #pragma unroll
            for (int fm = 0; fm < 2; fm++)
                ldm_x4(ah[fm], ldm_addr(sb + PXH, wm * 32 + fm * 16, ks * 16));
            #pragma unroll
            for (int mat = 0; mat < 3; mat++) {
                uint32_t bh[4];
                ldm_x4(bh, ldm_addr_b(sb + PWH, mat * 64 + wn * 16, ks * 16));
                #pragma unroll
                for (int fm = 0; fm < 2; fm++)
                    #pragma unroll
                    for (int fn = 0; fn < 2; fn++)
                        mma_f16(acc[mat][fm][fn], ah[fm], &bh[fn * 2]);
            }
        }
        __syncthreads();
    }

    // epilogue: all outputs fp16 hi-only; Q scaled by log2e/32
    #pragma unroll
    for (int mat = 0; mat < 3; mat++) {
        __half* gh = (mat == 0) ? g_Qh : ((mat == 1) ? g_Kh : g_Vh);
        const float scl = (mat == 0) ? (1.44269504f / 32.0f) : 1.0f;
        #pragma unroll
        for (int fm = 0; fm < 2; fm++)
            #pragma unroll
            for (int fn = 0; fn < 2; fn++) {
                const float* c = acc[mat][fm][fn];
                int r0 = m0 + wm * 32 + fm * 16 + g;
                int col = wn * 16 + fn * 8 + t * 2;
                reinterpret_cast<uint32_t*>(gh)[((size_t)r0 * HH + col) >> 1] =
                    pack2h(c[0] * scl, c[1] * scl);
                reinterpret_cast<uint32_t*>(gh)[((size_t)(r0 + 8) * HH + col) >> 1] =
                    pack2h(c[2] * scl, c[3] * scl);
            }
    }
}

// ---------------------------------------------------------------------------
// attn: flash attention (fp16 hi-only), no-max softmax, register P,
// 2-stage cp.async K/V pipeline (2 planes/stage). 256 CTAs balanced.
// ---------------------------------------------------------------------------
#define AQ    0
#define PLANE 9216
#define ABUF  9216
#define STG   (2 * PLANE)       // Kh, Vh
#define ALR   (ABUF + 2 * STG)  // 46080
#define ATOT  (ALR + 512)       // 46592

__global__ __launch_bounds__(256, 2) void attn_tc(float* __restrict__ Outp) {
    extern __shared__ char sm[];
    const uint32_t sb = (uint32_t)__cvta_generic_to_shared(sm);
    const int tid = threadIdx.x, wid = tid >> 5, lane = tid & 31;
    const int g = lane >> 2, t = lane & 3;
    const int qw = wid >> 1, kw = wid & 1;

    const int bid = blockIdx.x;
    int qt, b;
    if (bid < 108)      { qt = bid % 27;            b = bid / 27; }
    else if (bid < 148) { int s = bid - 108;        qt = 27 + (s >> 3); b = s & 7; }
    else                { int p = bid - 148;        qt = 26 - (p % 27); b = (p / 27) + 4; }

    const int q0 = qt * 64;
    const size_t base = (size_t)b * SS;

    // prefetch tile 0 (2 planes x 512 x 16B)
    #pragma unroll
    for (int i = 0; i < 4; i++) {
        int id = tid + i * 256;
        int plane = id >> 9, rem = id & 511;
        int row = rem >> 3, c = rem & 7;
        const __half* src = (plane == 0) ? g_Kh : g_Vh;
        cp16(sb + ABUF + plane * PLANE + row * LDB + c * 16,
             src + (base + row) * HH + c * 8);
    }
    CP_COMMIT();

    #pragma unroll
    for (int i = 0; i < 2; i++) {
        int id = tid + i * 256;
        int row = id >> 3, c = id & 7;
        *reinterpret_cast<uint4*>(sm + AQ + row * LDB + c * 16) =
            *reinterpret_cast<const uint4*>(g_Qh + (base + q0 + row) * HH + c * 8);
    }

    float o[8][4];
    #pragma unroll
    for (int i = 0; i < 8; i++)
        #pragma unroll
        for (int j = 0; j < 4; j++) o[i][j] = 0.f;
    float lsum0 = 0.f, lsum1 = 0.f;

    for (int kt = 0; kt <= qt; kt++) {
        const int k0 = kt * 64;
        CP_WAIT0();
        __syncthreads();

        if (kt < qt) {
            const int kn = k0 + 64;
            const uint32_t dstg = sb + ABUF + ((kt + 1) & 1) * STG;
            #pragma unroll
            for (int i = 0; i < 4; i++) {
                int id = tid + i * 256;
                int plane = id >> 9, rem = id & 511;
                int row = rem >> 3, c = rem & 7;
                const __half* src = (plane == 0) ? g_Kh : g_Vh;
                cp16(dstg + plane * PLANE + row * LDB + c * 16,
                     src + (base + kn + row) * HH + c * 8);
            }
        }
        CP_COMMIT();

        const uint32_t stg = sb + ABUF + (kt & 1) * STG;
        const uint32_t sKH = stg, sVH = stg + PLANE;

        // S' = Qh Kh^T (log2 domain)
        float s[4][4];
        #pragma unroll
        for (int i = 0; i < 4; i++)
            #pragma unroll
            for (int j = 0; j < 4; j++) s[i][j] = 0.f;

        #pragma unroll
        for (int hs = 0; hs < 4; hs++) {
            uint32_t ah[4], bh[4], bh2[4];
            ldm_x4(ah, ldm_addr(sb + AQ, qw * 16, hs * 16));
            ldm_x4(bh,  ldm_addr_b(sKH, kw * 32,      hs * 16));
            ldm_x4(bh2, ldm_addr_b(sKH, kw * 32 + 16, hs * 16));
            #pragma unroll
            for (int fn = 0; fn < 2; fn++) {
                mma_f16(s[fn],     ah, &bh[fn * 2]);
                mma_f16(s[2 + fn], ah, &bh2[fn * 2]);
            }
        }

        if (kt == qt) {
            #pragma unroll
            for (int f = 0; f < 4; f++) {
                int kg = k0 + kw * 32 + f * 8 + t * 2;
                int qg0 = q0 + qw * 16 + g, qg1 = qg0 + 8;
                if (kg     > qg0) s[f][0] = -200.f;
                if (kg + 1 > qg0) s[f][1] = -200.f;
                if (kg     > qg1) s[f][2] = -200.f;
                if (kg + 1 > qg1) s[f][3] = -200.f;
            }
        }

        // P = 2^{S'}; row sums; P -> fp16 rn A-fragments
        uint32_t pah[2][4];
        #pragma unroll
        for (int ks2 = 0; ks2 < 2; ks2++) {
            #pragma unroll
            for (int ff = 0; ff < 2; ff++) {
                const int f = ks2 * 2 + ff;
                float p0 = fast_exp2(s[f][0]);
                float p1 = fast_exp2(s[f][1]);
                float p2 = fast_exp2(s[f][2]);
                float p3 = fast_exp2(s[f][3]);
                lsum0 += p0 + p1;
                lsum1 += p2 + p3;
                pah[ks2][ff * 2]     = pack2h(p0, p1);
                pah[ks2][ff * 2 + 1] = pack2h(p2, p3);
            }
        }

        // O += Ph Vh over this warp's k-half, all 64 h columns
        #pragma unroll
        for (int ks2 = 0; ks2 < 2; ks2++) {
            uint32_t vh[4][4];
            #pragma unroll
            for (int c = 0; c < 4; c++)
                ldm_x4_t(vh[c], ldm_addr(sVH, kw * 32 + ks2 * 16, c * 16));
            #pragma unroll
            for (int j = 0; j < 8; j++)
                mma_f16(o[j], pah[ks2], &vh[j >> 1][(j & 1) * 2]);
        }
    }
    __syncthreads();

    lsum0 += __shfl_xor_sync(0xFFFFFFFFu, lsum0, 1);
    lsum0 += __shfl_xor_sync(0xFFFFFFFFu, lsum0, 2);
    lsum1 += __shfl_xor_sync(0xFFFFFFFFu, lsum1, 1);
    lsum1 += __shfl_xor_sync(0xFFFFFFFFu, lsum1, 2);
    float* lred = reinterpret_cast<float*>(sm + ALR);
    if (t == 0) {
        lred[(qw * 2 + kw) * 16 + g]     = lsum0;
        lred[(qw * 2 + kw) * 16 + 8 + g] = lsum1;
    }
    float* ored = reinterpret_cast<float*>(sm);
    if (kw == 1) {
        #pragma unroll
        for (int j = 0; j < 8; j++) {
            int col = j * 8 + t * 2;
            *reinterpret_cast<float2*>(&ored[(qw * 16 + g) * 64 + col]) =
                make_float2(o[j][0], o[j][1]);
            *reinterpret_cast<float2*>(&ored[(qw * 16 + g + 8) * 64 + col]) =
                make_float2(o[j][2], o[j][3]);
        }
    }
    __syncthreads();

    if (kw == 0) {
        float inv0 = 1.f / (lred[(qw * 2) * 16 + g]     + lred[(qw * 2 + 1) * 16 + g]);
        float inv1 = 1.f / (lred[(qw * 2) * 16 + 8 + g] + lred[(qw * 2 + 1) * 16 + 8 + g]);
        #pragma unroll
        for (int j = 0; j < 8; j++) {
            int col = j * 8 + t * 2;
            float2 a0 = *reinterpret_cast<float2*>(&ored[(qw * 16 + g) * 64 + col]);
            float2 a1 = *reinterpret_cast<float2*>(&ored[(qw * 16 + g + 8) * 64 + col]);
            size_t r0 = (base + q0 + qw * 16 + g) * HH + col;
            *reinterpret_cast<float2*>(Outp + r0) =
                make_float2((o[j][0] + a0.x) * inv0, (o[j][1] + a0.y) * inv0);
            *reinterpret_cast<float2*>(Outp + r0 + 8 * HH) =
                make_float2((o[j][2] + a1.x) * inv1, (o[j][3] + a1.y) * inv1);
        }
    }
}

// ---------------------------------------------------------------------------
extern "C" void kernel_launch(void* const* d_in, const int* in_sizes, int n_in,
                              void* d_out, int out_size)
{
    const float* X  = (const float*)d_in[0];
    const float* Wk = (const float*)d_in[1];
    const float* Wq = (const float*)d_in[2];
    const float* Wv = (const float*)d_in[3];
    float* Out = (float*)d_out;
    (void)in_sizes; (void)n_in; (void)out_size;

    cudaFuncSetAttribute(proj_tc, cudaFuncAttributeMaxDynamicSharedMemorySize, PTOT);
    cudaFuncSetAttribute(attn_tc, cudaFuncAttributeMaxDynamicSharedMemorySize, ATOT);

    prep_w<<<dim3(32, 3), 256>>>(Wq, Wk, Wv);
    proj_tc<<<MM / PTM, 256, PTOT>>>(X);
    attn_tc<<<256, 256, ATOT>>>(Out);
}